// round 9
// baseline (speedup 1.0000x reference)
#include <cuda_runtime.h>
#include <cuda_bf16.h>
#include <cstdint>

// ---------------------------------------------------------------------------
// MoE (top-2 of 8 experts), SwiGLU MLP, fp32 in/out, TF32 tensor-core compute.
//   T=2048, H=2048, I=1408, E=8, K=2.
// R7 profile: L1(shared)=70.6% binding, tensor=35.6% -> warp tiles were too
// small (256B LDS/MMA). This round: 64x64 warp tiles, 128-thread CTAs
// -> 128B LDS/MMA in both GEMMs.
// ---------------------------------------------------------------------------

#define T_TOK   2048
#define HID     2048
#define INTER   1408
#define NEXP    8
#define TOPK    2
#define NSLOT   (T_TOK * TOPK)   // 4096

#define BM      128
#define BK      16
#define BN1     64               // gemm1 output cols per block (phys B = 128: gate||up)
#define BN2     128              // gemm2 output cols per block
#define NT      128              // 4 warps
#define MAXTILES 40
#define AST     20               // A smem stride (conflict-free frag reads; rows 16B-aligned)
#define BSTW    136              // B smem stride, 136 % 32 == 8 -> conflict-free frag reads
#define ABUFB   (BM * AST * 4)   // bytes per A buffer (10240)

// ------------------------- device scratch (no allocs) ----------------------
__device__ int   g_cnt[NEXP];
__device__ int   g_off[NEXP];
__device__ int   g_ntiles;
__device__ int   g_tile_e[MAXTILES];
__device__ int   g_tile_m0[MAXTILES];
__device__ int   g_tok[NSLOT];
__device__ float g_w[NSLOT];
__device__ float g_xr [(size_t)T_TOK * HID];     // 16 MB tf32-rounded X
__device__ float g_act[(size_t)NSLOT * INTER];   // ~23 MB SwiGLU acts (tf32-rounded)

// ------------------------- helpers -----------------------------------------
__device__ __forceinline__ float to_tf32(float x) {
    uint32_t u;
    asm("cvt.rna.tf32.f32 %0, %1;" : "=r"(u) : "f"(x));
    return __uint_as_float(u);
}

__device__ __forceinline__ void cp_async16(uint32_t saddr, const void* gptr) {
    asm volatile("cp.async.ca.shared.global [%0], [%1], 16;"
                 :: "r"(saddr), "l"(gptr) : "memory");
}
__device__ __forceinline__ void cp_async_commit() {
    asm volatile("cp.async.commit_group;" ::: "memory");
}
__device__ __forceinline__ void cp_async_wait_all() {
    asm volatile("cp.async.wait_group 0;" ::: "memory");
}

#define MMA_TF32(c, a, b0, b1)                                             \
    asm volatile(                                                          \
        "mma.sync.aligned.m16n8k8.row.col.f32.tf32.tf32.f32 "              \
        "{%0,%1,%2,%3}, {%4,%5,%6,%7}, {%8,%9}, {%0,%1,%2,%3};"            \
        : "+f"((c)[0]), "+f"((c)[1]), "+f"((c)[2]), "+f"((c)[3])           \
        : "r"((a)[0]), "r"((a)[1]), "r"((a)[2]), "r"((a)[3]),              \
          "r"(b0), "r"(b1))

// ------------------------- X pre-rounding -----------------------------------
__global__ void round_x_kernel(const float* __restrict__ X) {
    size_t i = ((size_t)blockIdx.x * blockDim.x + threadIdx.x) * 4;
    const size_t n = (size_t)T_TOK * HID;
    if (i < n) {
        float4 v = *(const float4*)(X + i);
        v.x = to_tf32(v.x); v.y = to_tf32(v.y);
        v.z = to_tf32(v.z); v.w = to_tf32(v.w);
        *(float4*)(g_xr + i) = v;
    }
}

// ------------------------- routing ------------------------------------------
__global__ void route_kernel(const int* __restrict__ topk_idx,
                             const float* __restrict__ topk_w) {
    __shared__ int s_cnt[NEXP];
    __shared__ int s_off[NEXP];
    __shared__ int s_fill[NEXP];
    int tid = threadIdx.x;

    if (tid < NEXP) { s_cnt[tid] = 0; s_fill[tid] = 0; }
    __syncthreads();

    for (int s = tid; s < NSLOT; s += blockDim.x)
        atomicAdd(&s_cnt[topk_idx[s]], 1);
    __syncthreads();

    if (tid == 0) {
        int acc = 0, nt = 0;
        for (int e = 0; e < NEXP; e++) {
            s_off[e] = acc;
            g_off[e] = acc;
            g_cnt[e] = s_cnt[e];
            for (int m0 = 0; m0 < s_cnt[e]; m0 += BM) {
                g_tile_e[nt] = e;
                g_tile_m0[nt] = m0;
                nt++;
            }
            acc += s_cnt[e];
        }
        g_ntiles = nt;
        for (int t = nt; t < MAXTILES; t++) { g_tile_e[t] = 0; g_tile_m0[t] = 0; }
    }
    __syncthreads();

    for (int s = tid; s < NSLOT; s += blockDim.x) {
        int e = topk_idx[s];
        int p = atomicAdd(&s_fill[e], 1);
        int slot = s_off[e] + p;
        g_tok[slot] = s >> 1;          // token id (TOPK = 2)
        g_w[slot]   = topk_w[s];
    }
}

// ------------------------- GEMM1: fused gate+up + SwiGLU --------------------
// 4 warps; warp tile 64(M) x 64(phys N = 32 gate + 32 up matching columns).
__global__ __launch_bounds__(NT, 2) void gemm1_kernel(
    const float* __restrict__ Wg_all,
    const float* __restrict__ Wu_all) {
    int tile = blockIdx.x;
    if (tile >= g_ntiles) return;
    int e   = g_tile_e[tile];
    int m0  = g_tile_m0[tile];
    int seg = g_off[e];
    int cnt = g_cnt[e];
    int n0  = blockIdx.y * BN1;

    __shared__ float As[2][BM][AST];
    __shared__ float Bs[2][BK][BSTW];   // phys cols 0-63 gate, 64-127 up
    __shared__ int   s_tok[BM];

    int tid = threadIdx.x;
    { int ml = m0 + tid; s_tok[tid] = g_tok[seg + (ml < cnt ? ml : 0)]; }
    __syncthreads();

    // A: 128x16 tile, 4 x 16B cp.async per thread (rows arow+{0,32,64,96})
    const int arow = tid >> 2, acol = (tid & 3) << 2;
    const float* ap[4];
    uint32_t sa[4];
#pragma unroll
    for (int q = 0; q < 4; q++) {
        ap[q] = g_xr + (size_t)s_tok[arow + 32 * q] * HID + acol;
        sa[q] = (uint32_t)__cvta_generic_to_shared(&As[0][arow + 32 * q][acol]);
    }

    // B: 16x128 tile (gate||up), 4 float4 per thread from ONE source half
    const int brow = tid >> 3, bcolp = (tid & 7) << 4;
    const float* bsrc = (bcolp < 64)
        ? (Wg_all + (size_t)e * HID * INTER + (size_t)brow * INTER + n0 + bcolp)
        : (Wu_all + (size_t)e * HID * INTER + (size_t)brow * INTER + n0 + (bcolp - 64));

    float4 rb[4];

    auto cpA = [&](int b, int kt) {
        size_t k0 = (size_t)kt * BK;
#pragma unroll
        for (int q = 0; q < 4; q++) cp_async16(sa[q] + b * ABUFB, ap[q] + k0);
    };
    auto gloadB = [&](int kt) {
        size_t off = (size_t)kt * BK * INTER;
#pragma unroll
        for (int j = 0; j < 4; j++) rb[j] = *(const float4*)(bsrc + off + j * 4);
    };
    auto sstoreB = [&](int b) {
#pragma unroll
        for (int j = 0; j < 4; j++) {
            Bs[b][brow][bcolp + j*4 + 0] = to_tf32(rb[j].x);
            Bs[b][brow][bcolp + j*4 + 1] = to_tf32(rb[j].y);
            Bs[b][brow][bcolp + j*4 + 2] = to_tf32(rb[j].z);
            Bs[b][brow][bcolp + j*4 + 3] = to_tf32(rb[j].w);
        }
    };

    const int lane = tid & 31, wid = tid >> 5;
    const int wm  = (wid & 1) << 6;    // warp M base: 0 / 64
    const int wn2 = (wid >> 1) << 5;   // warp output-col base within 64: 0 / 32
    const int qr = lane >> 2, qc = lane & 3;

    float acc[4][8][4];                 // [im][jn: 0-3 gate, 4-7 up][frag]
#pragma unroll
    for (int i = 0; i < 4; i++)
#pragma unroll
        for (int j = 0; j < 8; j++)
#pragma unroll
            for (int v = 0; v < 4; v++) acc[i][j][v] = 0.f;

    auto compute = [&](int b) {
#pragma unroll
        for (int kk = 0; kk < BK; kk += 8) {
            uint32_t a[4][4];
#pragma unroll
            for (int im = 0; im < 4; im++) {
                int r = wm + im * 16 + qr;
                a[im][0] = __float_as_uint(As[b][r    ][kk + qc    ]);
                a[im][1] = __float_as_uint(As[b][r + 8][kk + qc    ]);
                a[im][2] = __float_as_uint(As[b][r    ][kk + qc + 4]);
                a[im][3] = __float_as_uint(As[b][r + 8][kk + qc + 4]);
            }
#pragma unroll
            for (int jn = 0; jn < 8; jn++) {
                int c = (jn < 4 ? wn2 + jn * 8 : 64 + wn2 + (jn - 4) * 8) + qr;
                uint32_t b0 = __float_as_uint(Bs[b][kk + qc    ][c]);
                uint32_t b1 = __float_as_uint(Bs[b][kk + qc + 4][c]);
#pragma unroll
                for (int im = 0; im < 4; im++)
                    MMA_TF32(acc[im][jn], a[im], b0, b1);
            }
        }
    };

    // single-sync pipelined mainloop (proven in R7)
    const int NK = HID / BK;   // 128
    cpA(0, 0);
    gloadB(0);
    sstoreB(0);
    cp_async_commit();
    cp_async_wait_all();
    __syncthreads();
    int buf = 0;
#pragma unroll 1
    for (int kt = 0; kt < NK - 1; kt++) {
        cpA(buf ^ 1, kt + 1);
        cp_async_commit();
        gloadB(kt + 1);
        compute(buf);
        sstoreB(buf ^ 1);
        cp_async_wait_all();
        __syncthreads();
        buf ^= 1;
    }
    compute(buf);

    // epilogue: SwiGLU with in-register gate/up pairing; pre-rounded store.
#pragma unroll
    for (int im = 0; im < 4; im++)
#pragma unroll
        for (int v2 = 0; v2 < 2; v2++) {
            int r  = wm + im * 16 + qr + v2 * 8;
            int ml = m0 + r;
            if (ml < cnt) {
                float* dst = g_act + (size_t)(seg + ml) * INTER + n0;
#pragma unroll
                for (int jn = 0; jn < 4; jn++) {
                    int c = wn2 + jn * 8 + qc * 2;
                    float g0 = acc[im][jn    ][v2 * 2], g1 = acc[im][jn    ][v2 * 2 + 1];
                    float u0 = acc[im][jn + 4][v2 * 2], u1 = acc[im][jn + 4][v2 * 2 + 1];
                    dst[c    ] = to_tf32(u0 * __fdividef(g0, 1.f + __expf(-g0)));
                    dst[c + 1] = to_tf32(u1 * __fdividef(g1, 1.f + __expf(-g1)));
                }
            }
        }
}

// ------------------------- GEMM2: down proj + weighted scatter --------------
// 4 warps; warp tile 64x64; BN=128 output cols per block.
__global__ __launch_bounds__(NT, 2) void gemm2_kernel(
    const float* __restrict__ Wd_all,
    float* __restrict__ out) {
    int tile = blockIdx.x;
    if (tile >= g_ntiles) return;
    int e   = g_tile_e[tile];
    int m0  = g_tile_m0[tile];
    int seg = g_off[e];
    int cnt = g_cnt[e];
    int n0  = blockIdx.y * BN2;

    __shared__ float As[2][BM][AST];
    __shared__ float Bs[2][BK][BSTW];
    __shared__ int   s_tok[BM];
    __shared__ float s_w[BM];

    int tid = threadIdx.x;
    {
        int ml = m0 + tid;
        int sl = seg + (ml < cnt ? ml : 0);
        s_tok[tid] = g_tok[sl];
        s_w[tid]   = g_w[sl];
    }

    const int arow = tid >> 2, acol = (tid & 3) << 2;
    const float* ap[4];
    uint32_t sa[4];
#pragma unroll
    for (int q = 0; q < 4; q++) {
        int mr = m0 + arow + 32 * q;
        int ar = seg + (mr < cnt ? mr : cnt - 1);   // clamp; masked in epilogue
        ap[q] = g_act + (size_t)ar * INTER + acol;
        sa[q] = (uint32_t)__cvta_generic_to_shared(&As[0][arow + 32 * q][acol]);
    }

    const int brow = tid >> 3, bcolp = (tid & 7) << 4;
    const float* bsrc = Wd_all + (size_t)e * INTER * HID + (size_t)brow * HID + n0 + bcolp;

    float4 rb[4];

    auto cpA = [&](int b, int kt) {
        size_t k0 = (size_t)kt * BK;
#pragma unroll
        for (int q = 0; q < 4; q++) cp_async16(sa[q] + b * ABUFB, ap[q] + k0);
    };
    auto gloadB = [&](int kt) {
        size_t off = (size_t)kt * BK * HID;
#pragma unroll
        for (int j = 0; j < 4; j++) rb[j] = *(const float4*)(bsrc + off + j * 4);
    };
    auto sstoreB = [&](int b) {
#pragma unroll
        for (int j = 0; j < 4; j++) {
            Bs[b][brow][bcolp + j*4 + 0] = to_tf32(rb[j].x);
            Bs[b][brow][bcolp + j*4 + 1] = to_tf32(rb[j].y);
            Bs[b][brow][bcolp + j*4 + 2] = to_tf32(rb[j].z);
            Bs[b][brow][bcolp + j*4 + 3] = to_tf32(rb[j].w);
        }
    };

    const int lane = tid & 31, wid = tid >> 5;
    const int wm = (wid & 1) << 6;     // 0 / 64
    const int wn = (wid >> 1) << 6;    // 0 / 64
    const int qr = lane >> 2, qc = lane & 3;

    float acc[4][8][4];
#pragma unroll
    for (int i = 0; i < 4; i++)
#pragma unroll
        for (int j = 0; j < 8; j++)
#pragma unroll
            for (int v = 0; v < 4; v++) acc[i][j][v] = 0.f;

    auto compute = [&](int b) {
#pragma unroll
        for (int kk = 0; kk < BK; kk += 8) {
            uint32_t a[4][4];
#pragma unroll
            for (int im = 0; im < 4; im++) {
                int r = wm + im * 16 + qr;
                a[im][0] = __float_as_uint(As[b][r    ][kk + qc    ]);
                a[im][1] = __float_as_uint(As[b][r + 8][kk + qc    ]);
                a[im][2] = __float_as_uint(As[b][r    ][kk + qc + 4]);
                a[im][3] = __float_as_uint(As[b][r + 8][kk + qc + 4]);
            }
#pragma unroll
            for (int jn = 0; jn < 8; jn++) {
                int c = wn + jn * 8 + qr;
                uint32_t b0 = __float_as_uint(Bs[b][kk + qc    ][c]);
                uint32_t b1 = __float_as_uint(Bs[b][kk + qc + 4][c]);
#pragma unroll
                for (int im = 0; im < 4; im++)
                    MMA_TF32(acc[im][jn], a[im], b0, b1);
            }
        }
    };

    __syncthreads();   // s_tok/s_w visible (epilogue); order before first fill
    const int NK = INTER / BK;   // 88
    cpA(0, 0);
    gloadB(0);
    sstoreB(0);
    cp_async_commit();
    cp_async_wait_all();
    __syncthreads();
    int buf = 0;
#pragma unroll 1
    for (int kt = 0; kt < NK - 1; kt++) {
        cpA(buf ^ 1, kt + 1);
        cp_async_commit();
        gloadB(kt + 1);
        compute(buf);
        sstoreB(buf ^ 1);
        cp_async_wait_all();
        __syncthreads();
        buf ^= 1;
    }
    compute(buf);

    // epilogue: weighted atomic scatter into out
#pragma unroll
    for (int im = 0; im < 4; im++)
#pragma unroll
        for (int v2 = 0; v2 < 2; v2++) {
            int r  = wm + im * 16 + qr + v2 * 8;
            int ml = m0 + r;
            if (ml < cnt) {
                float wgt = s_w[r];
                float* dst = out + (size_t)s_tok[r] * HID + n0;
#pragma unroll
                for (int jn = 0; jn < 8; jn++) {
                    int c = wn + jn * 8 + qc * 2;
                    atomicAdd(&dst[c    ], wgt * acc[im][jn][v2 * 2]);
                    atomicAdd(&dst[c + 1], wgt * acc[im][jn][v2 * 2 + 1]);
                }
            }
        }
}

// ------------------------- launch -------------------------------------------
extern "C" void kernel_launch(void* const* d_in, const int* in_sizes, int n_in,
                              void* d_out, int out_size) {
    const float* X   = (const float*)d_in[0];   // hidden_states [T, H]
    const int*   idx = (const int*)  d_in[1];   // top_k_index   [T, 2]
    const float* tkw = (const float*)d_in[2];   // top_k_weights [T, 2]
    const float* gw  = (const float*)d_in[3];   // gate_w [E, H, I]
    const float* uw  = (const float*)d_in[4];   // up_w   [E, H, I]
    const float* dw  = (const float*)d_in[5];   // down_w [E, I, H]
    float* out = (float*)d_out;                 // [T, H] fp32

    route_kernel<<<1, 256>>>(idx, tkw);
    round_x_kernel<<<(T_TOK * HID / 4 + 255) / 256, 256>>>(X);
    cudaMemsetAsync(out, 0, (size_t)out_size * sizeof(float));
    gemm1_kernel<<<dim3(MAXTILES, INTER / BN1), NT>>>(gw, uw);
    gemm2_kernel<<<dim3(MAXTILES, HID / BN2), NT>>>(dw, out);
}